// round 16
// baseline (speedup 1.0000x reference)
#include <cuda_runtime.h>
#include <cuda_bf16.h>
#include <cstdint>

// ============================================================================
// BitLinear: x[4,8192,1024] f32, W[1024,1024] f32, gamma/beta[1024]
// out = (scale_act*alpha) * (Qint @ T^T);  M=32768, K=1024, N=1024
// R16: persistent GEMM — R13 inner loop/pipeline unchanged, but each CTA
//      processes ~7 tiles with ONE flattened chunk pipeline across tile
//      boundaries (no per-tile prologue fill / epilogue drain).
//      Elementwise: R15 versions (measured ~63us, at DRAM floor).
// ============================================================================

#define M_ROWS 32768
#define K_DIM  1024
#define N_DIM  1024

// ---------------- device scratch ----------------
__device__ float         g_mu[M_ROWS];
__device__ float         g_rstd[M_ROWS];
__device__ unsigned int  g_absmax_bits;
__device__ float         g_wsum_abs;
__device__ float         g_wsum_absmask;
__device__ float         g_wsum_maskcnt;
__device__ __nv_bfloat16 g_qb[(size_t)M_ROWS * K_DIM];   // 64 MB
__device__ __nv_bfloat16 g_tb[(size_t)N_DIM * K_DIM];    // 2 MB

// ---------------- PTX helpers (baseline ISA) --------------------------------
__device__ __forceinline__ uint32_t smem_u32(const void* p) {
    uint32_t a;
    asm("{ .reg .u64 t; cvta.to.shared.u64 t, %1; cvt.u32.u64 %0, t; }"
        : "=r"(a) : "l"(p));
    return a;
}
__device__ __forceinline__ void ldm_x4(uint32_t* r, uint32_t addr) {
    asm volatile("ldmatrix.sync.aligned.m8n8.x4.shared.b16 {%0,%1,%2,%3}, [%4];"
                 : "=r"(r[0]), "=r"(r[1]), "=r"(r[2]), "=r"(r[3]) : "r"(addr));
}
__device__ __forceinline__ void mma_bf16(float* c, const uint32_t* a, const uint32_t* b) {
    asm volatile(
        "mma.sync.aligned.m16n8k16.row.col.f32.bf16.bf16.f32 "
        "{%0,%1,%2,%3}, {%4,%5,%6,%7}, {%8,%9}, {%0,%1,%2,%3};"
        : "+f"(c[0]), "+f"(c[1]), "+f"(c[2]), "+f"(c[3])
        : "r"(a[0]), "r"(a[1]), "r"(a[2]), "r"(a[3]), "r"(b[0]), "r"(b[1]));
}
#define CP_ASYNC16(sm, gm)                                                   \
    asm volatile("cp.async.cg.shared.global [%0], [%1], 16;" ::              \
                 "r"(sm), "l"(__cvta_generic_to_global(gm)))
#define CP_COMMIT() asm volatile("cp.async.commit_group;" ::: "memory")
#define CP_WAIT(n)  asm volatile("cp.async.wait_group %0;" :: "n"(n) : "memory")

// ============================================================================
// Kernel 1: zero accumulators
// ============================================================================
__global__ void zero_kernel() {
    g_absmax_bits  = 0u;
    g_wsum_abs     = 0.0f;
    g_wsum_absmask = 0.0f;
    g_wsum_maskcnt = 0.0f;
}

// ============================================================================
// Kernel 2: LN stats per row (128 thr/row, 2 float4/thread, MLP=2)
//           + global absmax; blocks 0..1023 also reduce |W| chunk
// ============================================================================
__global__ __launch_bounds__(128) void ln_stats_kernel(
    const float4* __restrict__ x4, const float4* __restrict__ gamma4,
    const float4* __restrict__ beta4, const float4* __restrict__ w4) {
    const int row = blockIdx.x;
    const int tid = threadIdx.x;
    const int w = tid >> 5, lane = tid & 31;

    float4 v1 = x4[(size_t)row * 256 + tid];
    float4 v2 = x4[(size_t)row * 256 + tid + 128];
    float s  = (v1.x + v1.y + v1.z + v1.w) + (v2.x + v2.y + v2.z + v2.w);
    float ss = fmaf(v1.x, v1.x, fmaf(v1.y, v1.y, fmaf(v1.z, v1.z, v1.w * v1.w)));
    ss = fmaf(v2.x, v2.x, fmaf(v2.y, v2.y, fmaf(v2.z, v2.z, fmaf(v2.w, v2.w, ss))));
#pragma unroll
    for (int o = 16; o > 0; o >>= 1) {
        s  += __shfl_xor_sync(0xffffffffu, s, o);
        ss += __shfl_xor_sync(0xffffffffu, ss, o);
    }
    __shared__ float rs[4], rss[4], bc[2], rm[4];
    if (lane == 0) { rs[w] = s; rss[w] = ss; }
    __syncthreads();
    if (tid == 0) {
        float ts = rs[0] + rs[1] + rs[2] + rs[3];
        float tss = rss[0] + rss[1] + rss[2] + rss[3];
        float mu  = ts * (1.0f / 1024.0f);
        float var = tss * (1.0f / 1024.0f) - mu * mu;
        float rstd = rsqrtf(var + 1e-5f);
        bc[0] = mu; bc[1] = rstd;
        g_mu[row] = mu; g_rstd[row] = rstd;
    }
    __syncthreads();
    const float mu = bc[0], rstd = bc[1];
    float4 g1 = gamma4[tid],       b1 = beta4[tid];
    float4 g2 = gamma4[tid + 128], b2 = beta4[tid + 128];
    float mm = fabsf(fmaf((v1.x - mu) * rstd, g1.x, b1.x));
    mm = fmaxf(mm, fabsf(fmaf((v1.y - mu) * rstd, g1.y, b1.y)));
    mm = fmaxf(mm, fabsf(fmaf((v1.z - mu) * rstd, g1.z, b1.z)));
    mm = fmaxf(mm, fabsf(fmaf((v1.w - mu) * rstd, g1.w, b1.w)));
    mm = fmaxf(mm, fabsf(fmaf((v2.x - mu) * rstd, g2.x, b2.x)));
    mm = fmaxf(mm, fabsf(fmaf((v2.y - mu) * rstd, g2.y, b2.y)));
    mm = fmaxf(mm, fabsf(fmaf((v2.z - mu) * rstd, g2.z, b2.z)));
    mm = fmaxf(mm, fabsf(fmaf((v2.w - mu) * rstd, g2.w, b2.w)));
#pragma unroll
    for (int o = 16; o > 0; o >>= 1)
        mm = fmaxf(mm, __shfl_xor_sync(0xffffffffu, mm, o));
    if (lane == 0) rm[w] = mm;
    __syncthreads();
    if (tid == 0)
        atomicMax(&g_absmax_bits,
                  __float_as_uint(fmaxf(fmaxf(rm[0], rm[1]), fmaxf(rm[2], rm[3]))));

    // ---- folded wabs: blocks 0..1023 reduce |W| over 256-float4 chunk ------
    if (row < 1024) {
        float4 wv1 = w4[row * 256 + tid];
        float4 wv2 = w4[row * 256 + tid + 128];
        float sw = fabsf(wv1.x) + fabsf(wv1.y) + fabsf(wv1.z) + fabsf(wv1.w)
                 + fabsf(wv2.x) + fabsf(wv2.y) + fabsf(wv2.z) + fabsf(wv2.w);
#pragma unroll
        for (int o = 16; o > 0; o >>= 1)
            sw += __shfl_xor_sync(0xffffffffu, sw, o);
        __syncthreads();
        if (lane == 0) rs[w] = sw;
        __syncthreads();
        if (tid == 0)
            atomicAdd(&g_wsum_abs, rs[0] + rs[1] + rs[2] + rs[3]);
    }
}

// ============================================================================
// Kernel 3: quantize LN(x) -> bf16 codes, 4 rows/thread (MLP=4)
//           + blocks 0..1023 ternarize W chunk + masked reductions
// ============================================================================
#define QQUART (M_ROWS * K_DIM / 4 / 4)   // 2097152 float4 per quarter

__global__ __launch_bounds__(256) void quant_kernel(
    const float4* __restrict__ x4, const float4* __restrict__ gamma4,
    const float4* __restrict__ beta4, const float4* __restrict__ w4) {
    const int idx = blockIdx.x * 256 + threadIdx.x;
    const int c4  = idx & 255;
    const float amax = fmaxf(__uint_as_float(g_absmax_bits), 1e-8f);
    const float inv  = 127.0f / amax;
    const int row0 = idx >> 8;
    const float4 g = gamma4[c4], b = beta4[c4];

    float4 v[4];
    float  mu[4], rstd[4];
#pragma unroll
    for (int q = 0; q < 4; ++q) {
        v[q]    = x4[idx + q * QQUART];
        mu[q]   = g_mu[row0 + q * (M_ROWS / 4)];
        rstd[q] = g_rstd[row0 + q * (M_ROWS / 4)];
    }
#pragma unroll
    for (int q = 0; q < 4; ++q) {
        float q0 = rintf(fminf(fmaxf(fmaf((v[q].x - mu[q]) * rstd[q], g.x, b.x) * inv, -127.f), 127.f));
        float q1 = rintf(fminf(fmaxf(fmaf((v[q].y - mu[q]) * rstd[q], g.y, b.y) * inv, -127.f), 127.f));
        float q2 = rintf(fminf(fmaxf(fmaf((v[q].z - mu[q]) * rstd[q], g.z, b.z) * inv, -127.f), 127.f));
        float q3 = rintf(fminf(fmaxf(fmaf((v[q].w - mu[q]) * rstd[q], g.w, b.w) * inv, -127.f), 127.f));
        __nv_bfloat162 p0 = __floats2bfloat162_rn(q0, q1);
        __nv_bfloat162 p1 = __floats2bfloat162_rn(q2, q3);
        uint2 pb;
        pb.x = *reinterpret_cast<uint32_t*>(&p0);
        pb.y = *reinterpret_cast<uint32_t*>(&p1);
        reinterpret_cast<uint2*>(g_qb)[idx + q * QQUART] = pb;
    }

    // ---- folded wtern: blocks 0..1023, one chunk of 256 float4 each --------
    if (blockIdx.x < 1024) {
        const int tid = threadIdx.x;
        const int widx = blockIdx.x * 256 + tid;
        const float delta = 0.7f * g_wsum_abs * (1.0f / (float)(N_DIM * K_DIM));
        float4 wv = w4[widx];
        float a[4] = {wv.x, wv.y, wv.z, wv.w};
        float tf[4];
        float sa = 0.f, cnt = 0.f;
#pragma unroll
        for (int j = 0; j < 4; ++j) {
            float av = fabsf(a[j]);
            if (av > delta) {
                tf[j] = (a[j] > 0.f) ? 1.0f : -1.0f;
                sa += av; cnt += 1.0f;
            } else tf[j] = 0.0f;
        }
        __nv_bfloat162 t0 = __floats2bfloat162_rn(tf[0], tf[1]);
        __nv_bfloat162 t1 = __floats2bfloat162_rn(tf[2], tf[3]);
        uint2 tb;
        tb.x = *reinterpret_cast<uint32_t*>(&t0);
        tb.y = *reinterpret_cast<uint32_t*>(&t1);
        reinterpret_cast<uint2*>(g_tb)[widx] = tb;
#pragma unroll
        for (int o = 16; o > 0; o >>= 1) {
            sa  += __shfl_xor_sync(0xffffffffu, sa, o);
            cnt += __shfl_xor_sync(0xffffffffu, cnt, o);
        }
        __shared__ float ra[8], rc[8];
        if ((tid & 31) == 0) { ra[tid >> 5] = sa; rc[tid >> 5] = cnt; }
        __syncthreads();
        if (tid == 0) {
            float ta = 0.f, tc = 0.f;
#pragma unroll
            for (int i = 0; i < 8; ++i) { ta += ra[i]; tc += rc[i]; }
            atomicAdd(&g_wsum_absmask, ta);
            atomicAdd(&g_wsum_maskcnt, tc);
        }
    }
}

// ============================================================================
// Kernel 4: PERSISTENT bf16 GEMM via mma.sync m16n8k16 (HMMA), f32 accum
// CTA tile 128x128, 128 thr = 4 warps (2M x 2N), warp tile 64x64
// Each CTA handles tiles bx, bx+G, ... with one flattened 3-stage chunk
// pipeline across tile boundaries (chunk j -> tile j/16, kt j&15).
// Single barrier/iter, ks frag double-buffer, direct-store epilogue.
// 2 CTAs/SM (96KB smem each).
// ============================================================================
#define GEMM_STAGES 3
#define STAGE_BYTES 32768
#define GEMM_SMEM   (GEMM_STAGES * STAGE_BYTES)   // 98304
#define NTILES      2048                          // (M/128)*(N/128)

static __device__ __forceinline__ void load_chunk(
    int j, int bx, int G, uint32_t smem_base, int tid) {
    const int t  = bx + (j >> 4) * G;
    const int kt = j & 15;
    const uint8_t* Ag = reinterpret_cast<const uint8_t*>(g_qb) +
                        (size_t)(t >> 3) * (128 * K_DIM * 2);
    const uint8_t* Bg = reinterpret_cast<const uint8_t*>(g_tb) +
                        (size_t)(t & 7) * (128 * K_DIM * 2);
    const uint32_t sA = smem_base + (uint32_t)(j % GEMM_STAGES) * STAGE_BYTES;
    const uint32_t sB = sA + 16384;
    const int koff = kt * 128;   // bytes
#pragma unroll
    for (int i = 0; i < 8; ++i) {    // 1024 x 16B per tile / 128 thr
        int v = i * 128 + tid;
        int row = v >> 3, c = v & 7;
        uint32_t sw = (uint32_t)(row * 128 + ((c ^ (row & 7)) << 4));
        size_t go = (size_t)row * (K_DIM * 2) + koff + c * 16;
        CP_ASYNC16(sA + sw, Ag + go);
        CP_ASYNC16(sB + sw, Bg + go);
    }
}

__global__ __launch_bounds__(128, 2) void gemm_kernel(float* __restrict__ out) {
    extern __shared__ char smem[];
    const uint32_t smem_base = smem_u32(smem);
    const int tid = threadIdx.x;
    const int wid = tid >> 5, lane = tid & 31;
    const int warp_m = wid & 1, warp_n = wid >> 1;   // 2 x 2
    const int bx = blockIdx.x, G = gridDim.x;

    const int ntile_local = (bx < NTILES) ? ((NTILES - 1 - bx) / G + 1) : 0;
    const int total = ntile_local * 16;
    if (total == 0) return;

    const float amax = fmaxf(__uint_as_float(g_absmax_bits), 1e-8f);
    const float osc  = (amax * (1.0f / 127.0f)) *
                       (g_wsum_absmask / fmaxf(g_wsum_maskcnt, 1.0f));

    // prologue: chunks 0, 1 -> stages 0, 1
    load_chunk(0, bx, G, smem_base, tid);
    CP_COMMIT();
    if (total > 1) load_chunk(1, bx, G, smem_base, tid);
    CP_COMMIT();

    float C[4][8][4];
#pragma unroll
    for (int i = 0; i < 4; ++i)
#pragma unroll
        for (int jj = 0; jj < 8; ++jj)
#pragma unroll
            for (int k = 0; k < 4; ++k) C[i][jj][k] = 0.0f;

    const int rA  = warp_m * 64 + (lane & 15);
    const int cA  = (lane >> 4);
    const int rBo = ((lane & 16) >> 1) + (lane & 7);
    const int cB  = (lane >> 3) & 1;

#pragma unroll 1
    for (int j = 0; j < total; ++j) {
        CP_WAIT(1);
        __syncthreads();   // single barrier: stage (j+2)%3's last readers
                           // finished in iter j-1 before this barrier.
        if (j + 2 < total) load_chunk(j + 2, bx, G, smem_base, tid);
        CP_COMMIT();

        const uint32_t aB = smem_base + (uint32_t)(j % GEMM_STAGES) * STAGE_BYTES;
        const uint32_t bB = aB + 16384;

        // ks-level software pipeline: prefetch frags for ks+1 before mma(ks)
        uint32_t a[2][4][4], b[2][4][4];
#pragma unroll
        for (int fm = 0; fm < 4; ++fm) {
            int row = rA + fm * 16;
            ldm_x4(a[0][fm], aB + row * 128 + ((cA ^ (row & 7)) << 4));
        }
#pragma unroll
        for (int p = 0; p < 4; ++p) {
            int row = warp_n * 64 + p * 16 + rBo;
            ldm_x4(b[0][p], bB + row * 128 + ((cB ^ (row & 7)) << 4));
        }
#pragma unroll
        for (int ks = 0; ks < 4; ++ks) {
            const int cur = ks & 1, nxt = cur ^ 1;
            if (ks < 3) {
#pragma unroll
                for (int fm = 0; fm < 4; ++fm) {
                    int row = rA + fm * 16;
                    ldm_x4(a[nxt][fm],
                           aB + row * 128 + ((((ks + 1) * 2 + cA) ^ (row & 7)) << 4));
                }
#pragma unroll
                for (int p = 0; p < 4; ++p) {
                    int row = warp_n * 64 + p * 16 + rBo;
                    ldm_x4(b[nxt][p],
                           bB + row * 128 + ((((ks + 1) * 2 + cB) ^ (row & 7)) << 4));
                }
            }
#pragma unroll
            for (int fm = 0; fm < 4; ++fm)
#pragma unroll
                for (int p = 0; p < 4; ++p) {
                    mma_bf16(C[fm][2 * p],     a[cur][fm], &b[cur][p][0]);
                    mma_bf16(C[fm][2 * p + 1], a[cur][fm], &b[cur][p][2]);
                }
        }

        // ------- tile finished: epilogue (overlaps next tile's loads) -------
        if ((j & 15) == 15) {
            const int t  = bx + (j >> 4) * G;
            const int m0 = (t >> 3) * 128, n0 = (t & 7) * 128;
#pragma unroll
            for (int fm = 0; fm < 4; ++fm) {
                const int r0 = m0 + warp_m * 64 + fm * 16 + (lane >> 2);
#pragma unroll
                for (int fn = 0; fn < 8; ++fn) {
                    const int col = n0 + warp_n * 64 + fn * 8 + (lane & 3) * 2;
                    float2 lo, hi;
                    lo.x = C[fm][fn][0] * osc;
                    lo.y = C[fm][fn][1] * osc;
                    hi.x = C[fm][fn][2] * osc;
                    hi.y = C[fm][fn][3] * osc;
                    *reinterpret_cast<float2*>(out + (size_t)r0 * N_DIM + col)       = lo;
                    *reinterpret_cast<float2*>(out + (size_t)(r0 + 8) * N_DIM + col) = hi;
                    C[fm][fn][0] = 0.0f; C[fm][fn][1] = 0.0f;
                    C[fm][fn][2] = 0.0f; C[fm][fn][3] = 0.0f;
                }
            }
        }
    }
}

// ============================================================================
// Launch: 4 kernels (GEMM persistent: grid = 2 x SM count)
// ============================================================================
extern "C" void kernel_launch(void* const* d_in, const int* in_sizes, int n_in,
                              void* d_out, int out_size) {
    const float4* x4 = (const float4*)d_in[0];
    const float4* w4 = (const float4*)d_in[1];
    const float4* g4 = (const float4*)d_in[2];
    const float4* b4 = (const float4*)d_in[3];
    float* out = (float*)d_out;

    zero_kernel<<<1, 1>>>();
    ln_stats_kernel<<<M_ROWS, 128>>>(x4, g4, b4, w4);
    quant_kernel<<<(M_ROWS * K_DIM / 4) / 256 / 4, 256>>>(x4, g4, b4, w4);

    static int grid_g = 0;
    if (grid_g == 0) {
        cudaFuncSetAttribute(gemm_kernel,
                             cudaFuncAttributeMaxDynamicSharedMemorySize, GEMM_SMEM);
        int sm = 148;
        cudaDeviceGetAttribute(&sm, cudaDevAttrMultiProcessorCount, 0);
        grid_g = 2 * sm;
        if (grid_g > NTILES) grid_g = NTILES;
    }
    gemm_kernel<<<grid_g, 128, GEMM_SMEM>>>(out);
}